// round 16
// baseline (speedup 1.0000x reference)
#include <cuda_runtime.h>
#include <cuda_bf16.h>
#include <cstdint>
#include <math.h>

#define BB 16
#define CC 64
#define SS 128
#define TT 512
#define NSPLIT 64
#define TITER (TT/NSPLIT)
#define PU 40    // u32 pitch for rows holding 32 u32 (64 bf16)
#define PY 72    // u32 pitch for rows holding 64 u32 (128 bf16)

// pair-slot permutation within groups of 8 pairs: logical pair p -> slot P8(p)
#define P8(k)   ((((k) & 3) << 1) | (((k) >> 2) & 1))
#define SLOT(p) ((((p) >> 3) << 3) | P8((p) & 7))

static __device__ uint32_t g_xS[(size_t)BB*TT*SS*32];   // [b][t][s][32 u32] bf16x2, c-pair-permuted
static __device__ uint32_t g_Y2[(size_t)BB*CC*TT*64];   // [b][a][t][64 u32] bf16x2, s-pair-permuted
static __device__ uint32_t g_Pp[(size_t)NSPLIT*BB*SS*64]; // logit partials, bf16x2 per j-pair
static __device__ uint32_t g_A [(size_t)BB*SS*64];      // [b][i][64 u32] bf16x2, j-pair-permuted
static __device__ float g_sx[BB*CC*SS];
static __device__ float g_t2[BB*SS];
static __device__ float g_t3[BB*SS];
static __device__ float g_r [BB*SS];
static __device__ uint32_t g_M[64*32];                  // [a][32 u32] bf16x2, c-pair-permuted
static __device__ uint32_t g_N[64*32];
static __device__ float g_u1[CC];
static __device__ float g_u2[CC];
static __device__ float g_g [CC];
static __device__ float g_dotb[1];

// ---- mma.sync bf16 m16n8k16, fp32 accum ----
#define MMA_BF16(d, a0, a1, a2, a3, b0, b1) \
    asm volatile("mma.sync.aligned.m16n8k16.row.col.f32.bf16.bf16.f32 " \
        "{%0,%1,%2,%3}, {%4,%5,%6,%7}, {%8,%9}, {%0,%1,%2,%3};" \
        : "+f"((d)[0]), "+f"((d)[1]), "+f"((d)[2]), "+f"((d)[3]) \
        : "r"(a0), "r"(a1), "r"(a2), "r"(a3), "r"(b0), "r"(b1))

__device__ __forceinline__ uint32_t packbf(float lo, float hi) {
    __nv_bfloat162 h = __floats2bfloat162_rn(lo, hi);
    return *reinterpret_cast<uint32_t*>(&h);
}
__device__ __forceinline__ uint32_t smem_u32(const void* p) {
    uint32_t a;
    asm("{ .reg .u64 t; cvta.to.shared.u64 t, %1; cvt.u32.u64 %0, t; }" : "=r"(a) : "l"(p));
    return a;
}
#define CP_ASYNC16(dst, src) asm volatile("cp.async.ca.shared.global [%0], [%1], 16;" :: "r"(dst), "l"(src))
#define CP_COMMIT()          asm volatile("cp.async.commit_group;" ::: "memory")
#define CP_WAIT0()           asm volatile("cp.async.wait_group 0;" ::: "memory")
#define CP_WAIT1()           asm volatile("cp.async.wait_group 1;" ::: "memory")

// ---- prep ----
__global__ void prep_kernel(const float* __restrict__ w11, const float* __restrict__ b11,
                            const float* __restrict__ w12, const float* __restrict__ b12,
                            const float* __restrict__ w13, const float* __restrict__ b13,
                            const float* __restrict__ w14, const float* __restrict__ b14) {
    int tid = threadIdx.x;
    int gtid = blockIdx.x * blockDim.x + tid;
    int nthr = blockDim.x * gridDim.x;
    for (int i = gtid; i < BB*CC*SS; i += nthr) g_sx[i] = 0.f;
    if (blockIdx.x == 0) {
        for (int idx = tid; idx < 64*32; idx += blockDim.x) {
            int a = idx >> 5, pe = idx & 31;
            int e0 = 2*pe, e1 = 2*pe + 1;
            float m0 = 0.f, m1 = 0.f, n0 = 0.f, n1 = 0.f;
            for (int c = 0; c < CC; c++) {
                m0 += w11[c*CC + a] * w12[c*CC + e0];
                m1 += w11[c*CC + a] * w12[c*CC + e1];
                n0 += w14[a*CC + c] * w13[c*CC + e0];
                n1 += w14[a*CC + c] * w13[c*CC + e1];
            }
            int pos = SLOT(pe);
            g_M[a*32 + pos] = packbf(m0, m1);
            g_N[a*32 + pos] = packbf(n0, n1);
        }
        for (int a = tid; a < CC; a += blockDim.x) {
            float u1 = 0.f, u2 = 0.f, gg = 0.f;
            for (int c = 0; c < CC; c++) {
                u1 += b11[c] * w12[c*CC + a];
                u2 += w11[c*CC + a] * b12[c];
                gg += w14[a*CC + c] * b13[c];
            }
            g_u1[a] = u1; g_u2[a] = u2; g_g[a] = gg;
        }
        if (tid == 0) {
            float d = 0.f;
            for (int c = 0; c < CC; c++) d += b11[c] * b12[c];
            g_dotb[0] = d * (float)TT;
        }
    }
}

// ---- transpose: x[b,c,s,t] -> xS[b][t][s][c-pairs bf16]; rowsums over t (MLP-batched) ----
#define TP_PITCH 66   // EVEN pitch required: phase-2 does float2 loads at (row*PITCH + 2*lane)
__global__ void __launch_bounds__(256) transpose_kernel(const float* __restrict__ x) {
    __shared__ float tile[128 * TP_PITCH];   // [(s*32+t)][c]
    int t0 = blockIdx.x * 32, s0 = blockIdx.y * 4, b = blockIdx.z;
    int tid = threadIdx.x, lane = tid & 31, w = tid >> 5;

    // phase 1: 32 fully-batched coalesced loads (MLP=32), then smem stores
    float vals[32];
#pragma unroll
    for (int r = 0; r < 32; r++) {
        int row = w*32 + r;            // 0..255
        int c = row >> 2, s = row & 3;
        vals[r] = x[((size_t)(b*CC + c)*SS + s0 + s)*TT + t0 + lane];
    }
#pragma unroll
    for (int r = 0; r < 32; r++) {
        int row = w*32 + r;
        int c = row >> 2, s = row & 3;
        tile[(s*32 + lane)*TP_PITCH + c] = vals[r];
    }
    __syncthreads();

    // phase 1.5: rowsums from smem — thread -> one (c,s) column, 32 independent LDS
    {
        int c = tid >> 2, s = tid & 3;   // 256 threads = 64c x 4s
        float sum = 0.f;
#pragma unroll
        for (int t = 0; t < 32; t++) sum += tile[(s*32 + t)*TP_PITCH + c];
        atomicAdd(&g_sx[(b*CC + c)*SS + s0 + s], sum);
    }

    // phase 2: write bf16 pairs, 128B lines
    int slot = SLOT(lane);
#pragma unroll
    for (int i = 0; i < 16; i++) {
        int sid = w*16 + i;            // 0..127
        int t = sid >> 2, s = sid & 3;
        float2 v = *(float2*)&tile[(s*32 + t)*TP_PITCH + 2*lane];
        g_xS[(((size_t)b*TT + t0 + t)*SS + s0 + s)*32 + slot] = packbf(v.x, v.y);
    }
}

// ---- bias terms (fully unrolled: MLP 64) ----
__global__ void bias_terms_kernel() {
    int b = blockIdx.x, i = threadIdx.x;
    float t2 = 0.f, t3 = 0.f;
#pragma unroll
    for (int a = 0; a < CC; a++) {
        float sv = g_sx[(b*CC + a)*SS + i];
        t2 += g_u2[a] * sv;
        t3 += g_u1[a] * sv;
    }
    g_t2[b*SS + i] = t2;
    g_t3[b*SS + i] = t3;
}

// ---- fused A: per (b,t): V'=U M^T (smem bf16), Y2'=N U^T (staged->gmem), P += U V'^T ----
#define FA_SMEM ((2*128*PU + 128*PU + 2*64*PU + 64*PY) * 4)
__global__ void __launch_bounds__(256, 2) fusedA_kernel() {
    extern __shared__ uint32_t smu[];
    uint32_t* Us0 = smu;
    uint32_t* Us1 = Us0 + 128*PU;
    uint32_t* Vs  = Us1 + 128*PU;
    uint32_t* Ms  = Vs  + 128*PU;
    uint32_t* Ns  = Ms  + 64*PU;
    uint32_t* Ysm = Ns  + 64*PU;
    uint32_t ua[2] = { smem_u32(Us0), smem_u32(Us1) };

    int b = blockIdx.x, split = blockIdx.y;
    int tid = threadIdx.x, lane = tid & 31, w = tid >> 5;
    int gid = lane >> 2, tq = lane & 3;
    int mw = w & 3, nw = w >> 2;
    int atile = (w & 3) * 16, shalf = (w >> 2) * 64;

    for (int i = tid; i < 64*8; i += 256) {
        int r = i >> 3, c4 = (i & 7) * 4;
        *(uint4*)&Ms[r*PU + c4] = *(const uint4*)&g_M[r*32 + c4];
        *(uint4*)&Ns[r*PU + c4] = *(const uint4*)&g_N[r*32 + c4];
    }
    {
        const uint32_t* su = g_xS + ((size_t)(b*TT + split*TITER)) * SS * 32;
        for (int i = tid; i < 128*8; i += 256) {
            int r = i >> 3, c4 = (i & 7) * 4;
            CP_ASYNC16(ua[0] + (uint32_t)(r*PU + c4)*4, su + r*32 + c4);
        }
        CP_COMMIT();
    }

    float pacc[2][8][4];
#pragma unroll
    for (int mt = 0; mt < 2; mt++)
#pragma unroll
        for (int n = 0; n < 8; n++)
#pragma unroll
            for (int q = 0; q < 4; q++) pacc[mt][n][q] = 0.f;

    for (int it = 0; it < TITER; it++) {
        int t = split*TITER + it;
        uint32_t* Us = (it & 1) ? Us1 : Us0;
        __syncthreads();
        if (it + 1 < TITER) {
            const uint32_t* su = g_xS + ((size_t)(b*TT + t + 1)) * SS * 32;
            uint32_t d = ua[(it + 1) & 1];
            for (int i = tid; i < 128*8; i += 256) {
                int r = i >> 3, c4 = (i & 7) * 4;
                CP_ASYNC16(d + (uint32_t)(r*PU + c4)*4, su + r*32 + c4);
            }
            CP_COMMIT();
            CP_WAIT1();
        } else {
            CP_WAIT0();
        }
        __syncthreads();

        // V-mix
        {
            float aV[8][4];
#pragma unroll
            for (int n = 0; n < 8; n++)
#pragma unroll
                for (int q = 0; q < 4; q++) aV[n][q] = 0.f;
#pragma unroll
            for (int kg = 0; kg < 4; kg++) {
                uint2 x0 = *(uint2*)&Us[(w*16 + gid    )*PU + kg*8 + 2*tq];
                uint2 x1 = *(uint2*)&Us[(w*16 + gid + 8)*PU + kg*8 + 2*tq];
#pragma unroll
                for (int n = 0; n < 8; n++) {
                    uint2 bm = *(uint2*)&Ms[(n*8 + gid)*PU + kg*8 + 2*tq];
                    MMA_BF16(aV[n], x0.x, x1.x, x0.y, x1.y, bm.x, bm.y);
                }
            }
            int row = w*16 + gid;
#pragma unroll
            for (int n = 0; n < 8; n++) {
                int pos = ((n >> 1) << 3) + P8(((n & 1) << 2) + tq);
                Vs[row*PU + pos]     = packbf(aV[n][0], aV[n][1]);
                Vs[(row+8)*PU + pos] = packbf(aV[n][2], aV[n][3]);
            }
        }
        // N-mix (transposed)
        {
            float aN[8][4];
#pragma unroll
            for (int n = 0; n < 8; n++)
#pragma unroll
                for (int q = 0; q < 4; q++) aN[n][q] = 0.f;
#pragma unroll
            for (int kg = 0; kg < 4; kg++) {
                uint2 n0 = *(uint2*)&Ns[(atile + gid    )*PU + kg*8 + 2*tq];
                uint2 n1 = *(uint2*)&Ns[(atile + gid + 8)*PU + kg*8 + 2*tq];
#pragma unroll
                for (int n = 0; n < 8; n++) {
                    uint2 bu = *(uint2*)&Us[(shalf + n*8 + gid)*PU + kg*8 + 2*tq];
                    MMA_BF16(aN[n], n0.x, n1.x, n0.y, n1.y, bu.x, bu.y);
                }
            }
            int ar = atile + gid;
#pragma unroll
            for (int n = 0; n < 8; n++) {
                int pos = (shalf >> 1) + ((n >> 1) << 3) + P8(((n & 1) << 2) + tq);
                Ysm[ar*PY + pos]     = packbf(aN[n][0], aN[n][1]);
                Ysm[(ar+8)*PY + pos] = packbf(aN[n][2], aN[n][3]);
            }
        }
        __syncthreads();

        // P += U V'^T
#pragma unroll
        for (int kg = 0; kg < 4; kg++) {
            uint2 xa[2][2];
#pragma unroll
            for (int mt = 0; mt < 2; mt++) {
                int base = mw*32 + mt*16;
                xa[mt][0] = *(uint2*)&Us[(base + gid    )*PU + kg*8 + 2*tq];
                xa[mt][1] = *(uint2*)&Us[(base + gid + 8)*PU + kg*8 + 2*tq];
            }
#pragma unroll
            for (int n = 0; n < 8; n++) {
                uint2 bv = *(uint2*)&Vs[(nw*64 + n*8 + gid)*PU + kg*8 + 2*tq];
#pragma unroll
                for (int mt = 0; mt < 2; mt++)
                    MMA_BF16(pacc[mt][n], xa[mt][0].x, xa[mt][1].x, xa[mt][0].y, xa[mt][1].y, bv.x, bv.y);
            }
        }

        for (int i = tid; i < 64*16; i += 256) {
            int a = i >> 4, q4 = (i & 15) * 4;
            *(uint4*)(g_Y2 + (((size_t)(b*CC + a))*TT + t)*64 + q4) = *(uint4*)&Ysm[a*PY + q4];
        }
    }

    // write split-private partials as bf16x2
    uint32_t* Pb = g_Pp + ((size_t)(split*BB + b)) * SS * 64;
#pragma unroll
    for (int mt = 0; mt < 2; mt++) {
        int i = mw*32 + mt*16 + gid;
#pragma unroll
        for (int n = 0; n < 8; n++) {
            int jp = nw*32 + n*4 + tq;     // pair index = j/2
            Pb[i*64 + jp]     = packbf(pacc[mt][n][0], pacc[mt][n][1]);
            Pb[(i+8)*64 + jp] = packbf(pacc[mt][n][2], pacc[mt][n][3]);
        }
    }
}

// ---- softmax_plus1 + rowsums; sums bf16 split partials; writes A bf16x2 (j-pair-permuted) ----
__global__ void softmax_kernel() {
    __shared__ float wm[4], ws[4];
    int bid = blockIdx.x;
    int b = bid >> 7, i = bid & 127;
    int j = threadIdx.x;
    const float inv_scale = 1.0f / sqrtf((float)(CC * TT));
    int shift = (j & 1) * 16;
    const uint32_t* base = g_Pp + (size_t)b*SS*64 + i*64 + (j >> 1);
    float p = 0.f;
#pragma unroll 16
    for (int sp = 0; sp < NSPLIT; sp++) {
        uint32_t v = base[(size_t)sp*BB*SS*64];
        p += __uint_as_float((v >> shift) << 16);
    }
    float v = (p + g_t2[b*SS + i] + g_t3[b*SS + j] + g_dotb[0]) * inv_scale;
    float m = v;
#pragma unroll
    for (int o = 16; o > 0; o >>= 1) m = fmaxf(m, __shfl_xor_sync(0xffffffff, m, o));
    int w = j >> 5, l = j & 31;
    if (l == 0) wm[w] = m;
    __syncthreads();
    m = fmaxf(fmaxf(wm[0], wm[1]), fmaxf(wm[2], wm[3]));
    float e = expf(v - m);
    float s = e;
#pragma unroll
    for (int o = 16; o > 0; o >>= 1) s += __shfl_xor_sync(0xffffffff, s, o);
    if (l == 0) ws[w] = s;
    __syncthreads();
    s = ws[0] + ws[1] + ws[2] + ws[3];
    float denom = 1.0f + s;
    float val = e / denom;
    float nb = __shfl_xor_sync(0xffffffff, val, 1);
    if (!(j & 1)) {
        int pp = j >> 1;
        g_A[((size_t)b*SS + i)*64 + SLOT(pp)] = packbf(val, nb);
    }
    if (j == 0) g_r[b*SS + i] = s / denom;
}

// ---- stage C: per (b,a,tk128): two t-halves, A resident, Y prefetch overlap ----
#define SC_SMEM ((128*PY + 2*64*PY) * 4)
__global__ void __launch_bounds__(256, 2) stageC_kernel(const float* __restrict__ x,
                                                        const float* __restrict__ alpha,
                                                        const float* __restrict__ b14,
                                                        float* __restrict__ out) {
    extern __shared__ uint32_t smc[];
    uint32_t* As  = smc;               // [128 i][PY]
    uint32_t* Ys0 = smc + 128*PY;      // [64 t'][PY]
    uint32_t* Ys1 = Ys0 + 64*PY;
    uint32_t as_addr = smem_u32(As), ys0_addr = smem_u32(Ys0), ys1_addr = smem_u32(Ys1);
    int tk = blockIdx.x, a = blockIdx.y, b = blockIdx.z;
    int tbase = tk * 128;
    int tid = threadIdx.x, lane = tid & 31, w = tid >> 5;
    int gid = lane >> 2, tq = lane & 3;

    const uint32_t* Ab = g_A + (size_t)b*SS*64;
    const uint32_t* Yb = g_Y2 + (((size_t)(b*CC + a))*TT + tbase) * 64;
    for (int i = tid; i < 128*16; i += 256) {
        int r = i >> 4, c4 = (i & 15) * 4;
        CP_ASYNC16(as_addr + (uint32_t)(r*PY + c4)*4, Ab + r*64 + c4);
    }
    for (int i = tid; i < 64*16; i += 256) {
        int r = i >> 4, c4 = (i & 15) * 4;
        CP_ASYNC16(ys0_addr + (uint32_t)(r*PY + c4)*4, Yb + (size_t)r*64 + c4);
    }
    CP_COMMIT();
    for (int i = tid; i < 64*16; i += 256) {
        int r = i >> 4, c4 = (i & 15) * 4;
        CP_ASYNC16(ys1_addr + (uint32_t)(r*PY + c4)*4, Yb + (size_t)(r + 64)*64 + c4);
    }
    CP_COMMIT();
    CP_WAIT1();
    __syncthreads();

    int i0 = w*16 + gid;
    float ga = g_g[a], ba = b14[a];
    float add0 = g_r[b*SS + i0    ] * ga + ba;
    float add1 = g_r[b*SS + i0 + 8] * ga + ba;

#pragma unroll
    for (int h = 0; h < 2; h++) {
        if (h == 1) { CP_WAIT0(); __syncthreads(); }
        uint32_t* Ys = h ? Ys1 : Ys0;
        int t0 = tbase + h*64;

        float acc[8][4];
#pragma unroll
        for (int n = 0; n < 8; n++)
#pragma unroll
            for (int q = 0; q < 4; q++) acc[n][q] = 0.f;

#pragma unroll
        for (int kg = 0; kg < 8; kg++) {
            uint2 x0 = *(uint2*)&As[(w*16 + gid    )*PY + kg*8 + 2*tq];
            uint2 x1 = *(uint2*)&As[(w*16 + gid + 8)*PY + kg*8 + 2*tq];
#pragma unroll
            for (int n = 0; n < 8; n++) {
                uint2 bv = *(uint2*)&Ys[(n*8 + gid)*PY + kg*8 + 2*tq];
                MMA_BF16(acc[n], x0.x, x1.x, x0.y, x1.y, bv.x, bv.y);
            }
        }

        size_t row0 = (((size_t)b*CC + a)*SS + i0    )*TT + t0;
        size_t row1 = (((size_t)b*CC + a)*SS + i0 + 8)*TT + t0;
        size_t arow0 = ((size_t)a*SS + i0    )*TT + t0;
        size_t arow1 = ((size_t)a*SS + i0 + 8)*TT + t0;
#pragma unroll
        for (int n = 0; n < 8; n++) {
            int tc = n*8 + 2*tq;
            float2 xv0 = *(const float2*)&x[row0 + tc];
            float2 av0 = *(const float2*)&alpha[arow0 + tc];
            float2 o0;
            o0.x = av0.x * (acc[n][0] + add0) + xv0.x;
            o0.y = av0.y * (acc[n][1] + add0) + xv0.y;
            *(float2*)&out[row0 + tc] = o0;
            float2 xv1 = *(const float2*)&x[row1 + tc];
            float2 av1 = *(const float2*)&alpha[arow1 + tc];
            float2 o1;
            o1.x = av1.x * (acc[n][2] + add1) + xv1.x;
            o1.y = av1.y * (acc[n][3] + add1) + xv1.y;
            *(float2*)&out[row1 + tc] = o1;
        }
    }
}

// ---- launcher ----
extern "C" void kernel_launch(void* const* d_in, const int* in_sizes, int n_in,
                              void* d_out, int out_size) {
    const float* x    = (const float*)d_in[0];
    const float* w11  = (const float*)d_in[1];
    const float* b11  = (const float*)d_in[2];
    const float* w12  = (const float*)d_in[3];
    const float* b12  = (const float*)d_in[4];
    const float* w13  = (const float*)d_in[5];
    const float* b13  = (const float*)d_in[6];
    const float* w14  = (const float*)d_in[7];
    const float* b14  = (const float*)d_in[8];
    const float* alpha= (const float*)d_in[9];
    float* out = (float*)d_out;

    cudaFuncSetAttribute((const void*)fusedA_kernel, cudaFuncAttributeMaxDynamicSharedMemorySize, FA_SMEM);
    cudaFuncSetAttribute((const void*)stageC_kernel, cudaFuncAttributeMaxDynamicSharedMemorySize, SC_SMEM);

    prep_kernel<<<256, 256>>>(w11, b11, w12, b12, w13, b13, w14, b14);
    transpose_kernel<<<dim3(TT/32, SS/4, BB), 256>>>(x);
    bias_terms_kernel<<<BB, 128>>>();
    fusedA_kernel<<<dim3(BB, NSPLIT), 256, FA_SMEM>>>();
    softmax_kernel<<<BB*SS, 128>>>();
    stageC_kernel<<<dim3(TT/128, CC, BB), 256, SC_SMEM>>>(x, alpha, b14, out);
}

// round 17
// speedup vs baseline: 1.4724x; 1.4724x over previous
#include <cuda_runtime.h>
#include <cuda_bf16.h>
#include <cstdint>
#include <math.h>

#define BB 16
#define CC 64
#define SS 128
#define TT 512
#define NSPLIT 64
#define TITER (TT/NSPLIT)
#define PU 40    // u32 pitch for rows holding 32 u32 (64 bf16)
#define PY 72    // u32 pitch for rows holding 64 u32 (128 bf16)

// pair-slot permutation within groups of 8 pairs: logical pair p -> slot P8(p)
#define P8(k)   ((((k) & 3) << 1) | (((k) >> 2) & 1))
#define SLOT(p) ((((p) >> 3) << 3) | P8((p) & 7))

static __device__ uint32_t g_xS[(size_t)BB*TT*SS*32];   // [b][t][s][32 u32] bf16x2, c-pair-permuted
static __device__ uint32_t g_Y2[(size_t)BB*CC*TT*64];   // [b][a][t][64 u32] bf16x2, s-pair-permuted
static __device__ uint32_t g_Pp[(size_t)NSPLIT*BB*SS*64]; // logit partials, bf16x2 per j-pair
static __device__ uint32_t g_A [(size_t)BB*SS*64];      // [b][i][64 u32] bf16x2, j-pair-permuted
static __device__ float g_sx[BB*CC*SS];
static __device__ float g_t2[BB*SS];
static __device__ float g_t3[BB*SS];
static __device__ float g_r [BB*SS];
static __device__ uint32_t g_M[64*32];                  // [a][32 u32] bf16x2, c-pair-permuted
static __device__ uint32_t g_N[64*32];
static __device__ float g_u1[CC];
static __device__ float g_u2[CC];
static __device__ float g_g [CC];
static __device__ float g_dotb[1];

// ---- mma.sync bf16 m16n8k16, fp32 accum ----
#define MMA_BF16(d, a0, a1, a2, a3, b0, b1) \
    asm volatile("mma.sync.aligned.m16n8k16.row.col.f32.bf16.bf16.f32 " \
        "{%0,%1,%2,%3}, {%4,%5,%6,%7}, {%8,%9}, {%0,%1,%2,%3};" \
        : "+f"((d)[0]), "+f"((d)[1]), "+f"((d)[2]), "+f"((d)[3]) \
        : "r"(a0), "r"(a1), "r"(a2), "r"(a3), "r"(b0), "r"(b1))

__device__ __forceinline__ uint32_t packbf(float lo, float hi) {
    __nv_bfloat162 h = __floats2bfloat162_rn(lo, hi);
    return *reinterpret_cast<uint32_t*>(&h);
}
__device__ __forceinline__ uint32_t smem_u32(const void* p) {
    uint32_t a;
    asm("{ .reg .u64 t; cvta.to.shared.u64 t, %1; cvt.u32.u64 %0, t; }" : "=r"(a) : "l"(p));
    return a;
}
#define CP_ASYNC16(dst, src) asm volatile("cp.async.ca.shared.global [%0], [%1], 16;" :: "r"(dst), "l"(src))
#define CP_COMMIT()          asm volatile("cp.async.commit_group;" ::: "memory")
#define CP_WAIT0()           asm volatile("cp.async.wait_group 0;" ::: "memory")
#define CP_WAIT1()           asm volatile("cp.async.wait_group 1;" ::: "memory")

// ---- prep ----
__global__ void prep_kernel(const float* __restrict__ w11, const float* __restrict__ b11,
                            const float* __restrict__ w12, const float* __restrict__ b12,
                            const float* __restrict__ w13, const float* __restrict__ b13,
                            const float* __restrict__ w14, const float* __restrict__ b14) {
    int tid = threadIdx.x;
    int gtid = blockIdx.x * blockDim.x + tid;
    int nthr = blockDim.x * gridDim.x;
    for (int i = gtid; i < BB*CC*SS; i += nthr) g_sx[i] = 0.f;
    if (blockIdx.x == 0) {
        for (int idx = tid; idx < 64*32; idx += blockDim.x) {
            int a = idx >> 5, pe = idx & 31;
            int e0 = 2*pe, e1 = 2*pe + 1;
            float m0 = 0.f, m1 = 0.f, n0 = 0.f, n1 = 0.f;
            for (int c = 0; c < CC; c++) {
                m0 += w11[c*CC + a] * w12[c*CC + e0];
                m1 += w11[c*CC + a] * w12[c*CC + e1];
                n0 += w14[a*CC + c] * w13[c*CC + e0];
                n1 += w14[a*CC + c] * w13[c*CC + e1];
            }
            int pos = SLOT(pe);
            g_M[a*32 + pos] = packbf(m0, m1);
            g_N[a*32 + pos] = packbf(n0, n1);
        }
        for (int a = tid; a < CC; a += blockDim.x) {
            float u1 = 0.f, u2 = 0.f, gg = 0.f;
            for (int c = 0; c < CC; c++) {
                u1 += b11[c] * w12[c*CC + a];
                u2 += w11[c*CC + a] * b12[c];
                gg += w14[a*CC + c] * b13[c];
            }
            g_u1[a] = u1; g_u2[a] = u2; g_g[a] = gg;
        }
        if (tid == 0) {
            float d = 0.f;
            for (int c = 0; c < CC; c++) d += b11[c] * b12[c];
            g_dotb[0] = d * (float)TT;
        }
    }
}

// ---- transpose: x[b,c,s,t] -> xS[b][t][s][c-pairs bf16]; rowsums over t (MLP-batched) ----
#define TP_PITCH 66   // EVEN pitch required: phase-2 does float2 loads at (row*PITCH + 2*lane)
__global__ void __launch_bounds__(256) transpose_kernel(const float* __restrict__ x) {
    __shared__ float tile[128 * TP_PITCH];   // [(s*32+t)][c]
    int t0 = blockIdx.x * 32, s0 = blockIdx.y * 4, b = blockIdx.z;
    int tid = threadIdx.x, lane = tid & 31, w = tid >> 5;

    // phase 1: 32 fully-batched coalesced loads (MLP=32), then smem stores
    float vals[32];
#pragma unroll
    for (int r = 0; r < 32; r++) {
        int row = w*32 + r;            // 0..255
        int c = row >> 2, s = row & 3;
        vals[r] = x[((size_t)(b*CC + c)*SS + s0 + s)*TT + t0 + lane];
    }
#pragma unroll
    for (int r = 0; r < 32; r++) {
        int row = w*32 + r;
        int c = row >> 2, s = row & 3;
        tile[(s*32 + lane)*TP_PITCH + c] = vals[r];
    }
    __syncthreads();

    // phase 1.5: rowsums from smem — thread -> one (c,s) column, 32 independent LDS
    {
        int c = tid >> 2, s = tid & 3;   // 256 threads = 64c x 4s
        float sum = 0.f;
#pragma unroll
        for (int t = 0; t < 32; t++) sum += tile[(s*32 + t)*TP_PITCH + c];
        atomicAdd(&g_sx[(b*CC + c)*SS + s0 + s], sum);
    }

    // phase 2: write bf16 pairs, 128B lines
    int slot = SLOT(lane);
#pragma unroll
    for (int i = 0; i < 16; i++) {
        int sid = w*16 + i;            // 0..127
        int t = sid >> 2, s = sid & 3;
        float2 v = *(float2*)&tile[(s*32 + t)*TP_PITCH + 2*lane];
        g_xS[(((size_t)b*TT + t0 + t)*SS + s0 + s)*32 + slot] = packbf(v.x, v.y);
    }
}

// ---- bias terms (fully unrolled: MLP 64) ----
__global__ void bias_terms_kernel() {
    int b = blockIdx.x, i = threadIdx.x;
    float t2 = 0.f, t3 = 0.f;
#pragma unroll
    for (int a = 0; a < CC; a++) {
        float sv = g_sx[(b*CC + a)*SS + i];
        t2 += g_u2[a] * sv;
        t3 += g_u1[a] * sv;
    }
    g_t2[b*SS + i] = t2;
    g_t3[b*SS + i] = t3;
}

// ---- fused A: per (b,t): V'=U M^T (smem bf16), Y2'=N U^T (staged->gmem), P += U V'^T ----
#define FA_SMEM ((2*128*PU + 128*PU + 2*64*PU + 64*PY) * 4)
__global__ void __launch_bounds__(256, 2) fusedA_kernel() {
    extern __shared__ uint32_t smu[];
    uint32_t* Us0 = smu;
    uint32_t* Us1 = Us0 + 128*PU;
    uint32_t* Vs  = Us1 + 128*PU;
    uint32_t* Ms  = Vs  + 128*PU;
    uint32_t* Ns  = Ms  + 64*PU;
    uint32_t* Ysm = Ns  + 64*PU;
    uint32_t ua[2] = { smem_u32(Us0), smem_u32(Us1) };

    int b = blockIdx.x, split = blockIdx.y;
    int tid = threadIdx.x, lane = tid & 31, w = tid >> 5;
    int gid = lane >> 2, tq = lane & 3;
    int mw = w & 3, nw = w >> 2;
    int atile = (w & 3) * 16, shalf = (w >> 2) * 64;

    for (int i = tid; i < 64*8; i += 256) {
        int r = i >> 3, c4 = (i & 7) * 4;
        *(uint4*)&Ms[r*PU + c4] = *(const uint4*)&g_M[r*32 + c4];
        *(uint4*)&Ns[r*PU + c4] = *(const uint4*)&g_N[r*32 + c4];
    }
    {
        const uint32_t* su = g_xS + ((size_t)(b*TT + split*TITER)) * SS * 32;
        for (int i = tid; i < 128*8; i += 256) {
            int r = i >> 3, c4 = (i & 7) * 4;
            CP_ASYNC16(ua[0] + (uint32_t)(r*PU + c4)*4, su + r*32 + c4);
        }
        CP_COMMIT();
    }

    float pacc[2][8][4];
#pragma unroll
    for (int mt = 0; mt < 2; mt++)
#pragma unroll
        for (int n = 0; n < 8; n++)
#pragma unroll
            for (int q = 0; q < 4; q++) pacc[mt][n][q] = 0.f;

    for (int it = 0; it < TITER; it++) {
        int t = split*TITER + it;
        uint32_t* Us = (it & 1) ? Us1 : Us0;
        __syncthreads();
        if (it + 1 < TITER) {
            const uint32_t* su = g_xS + ((size_t)(b*TT + t + 1)) * SS * 32;
            uint32_t d = ua[(it + 1) & 1];
            for (int i = tid; i < 128*8; i += 256) {
                int r = i >> 3, c4 = (i & 7) * 4;
                CP_ASYNC16(d + (uint32_t)(r*PU + c4)*4, su + r*32 + c4);
            }
            CP_COMMIT();
            CP_WAIT1();
        } else {
            CP_WAIT0();
        }
        __syncthreads();

        // V-mix
        {
            float aV[8][4];
#pragma unroll
            for (int n = 0; n < 8; n++)
#pragma unroll
                for (int q = 0; q < 4; q++) aV[n][q] = 0.f;
#pragma unroll
            for (int kg = 0; kg < 4; kg++) {
                uint2 x0 = *(uint2*)&Us[(w*16 + gid    )*PU + kg*8 + 2*tq];
                uint2 x1 = *(uint2*)&Us[(w*16 + gid + 8)*PU + kg*8 + 2*tq];
#pragma unroll
                for (int n = 0; n < 8; n++) {
                    uint2 bm = *(uint2*)&Ms[(n*8 + gid)*PU + kg*8 + 2*tq];
                    MMA_BF16(aV[n], x0.x, x1.x, x0.y, x1.y, bm.x, bm.y);
                }
            }
            int row = w*16 + gid;
#pragma unroll
            for (int n = 0; n < 8; n++) {
                int pos = ((n >> 1) << 3) + P8(((n & 1) << 2) + tq);
                Vs[row*PU + pos]     = packbf(aV[n][0], aV[n][1]);
                Vs[(row+8)*PU + pos] = packbf(aV[n][2], aV[n][3]);
            }
        }
        // N-mix (transposed)
        {
            float aN[8][4];
#pragma unroll
            for (int n = 0; n < 8; n++)
#pragma unroll
                for (int q = 0; q < 4; q++) aN[n][q] = 0.f;
#pragma unroll
            for (int kg = 0; kg < 4; kg++) {
                uint2 n0 = *(uint2*)&Ns[(atile + gid    )*PU + kg*8 + 2*tq];
                uint2 n1 = *(uint2*)&Ns[(atile + gid + 8)*PU + kg*8 + 2*tq];
#pragma unroll
                for (int n = 0; n < 8; n++) {
                    uint2 bu = *(uint2*)&Us[(shalf + n*8 + gid)*PU + kg*8 + 2*tq];
                    MMA_BF16(aN[n], n0.x, n1.x, n0.y, n1.y, bu.x, bu.y);
                }
            }
            int ar = atile + gid;
#pragma unroll
            for (int n = 0; n < 8; n++) {
                int pos = (shalf >> 1) + ((n >> 1) << 3) + P8(((n & 1) << 2) + tq);
                Ysm[ar*PY + pos]     = packbf(aN[n][0], aN[n][1]);
                Ysm[(ar+8)*PY + pos] = packbf(aN[n][2], aN[n][3]);
            }
        }
        __syncthreads();

        // P += U V'^T
#pragma unroll
        for (int kg = 0; kg < 4; kg++) {
            uint2 xa[2][2];
#pragma unroll
            for (int mt = 0; mt < 2; mt++) {
                int base = mw*32 + mt*16;
                xa[mt][0] = *(uint2*)&Us[(base + gid    )*PU + kg*8 + 2*tq];
                xa[mt][1] = *(uint2*)&Us[(base + gid + 8)*PU + kg*8 + 2*tq];
            }
#pragma unroll
            for (int n = 0; n < 8; n++) {
                uint2 bv = *(uint2*)&Vs[(nw*64 + n*8 + gid)*PU + kg*8 + 2*tq];
#pragma unroll
                for (int mt = 0; mt < 2; mt++)
                    MMA_BF16(pacc[mt][n], xa[mt][0].x, xa[mt][1].x, xa[mt][0].y, xa[mt][1].y, bv.x, bv.y);
            }
        }

        for (int i = tid; i < 64*16; i += 256) {
            int a = i >> 4, q4 = (i & 15) * 4;
            *(uint4*)(g_Y2 + (((size_t)(b*CC + a))*TT + t)*64 + q4) = *(uint4*)&Ysm[a*PY + q4];
        }
    }

    // write split-private partials as bf16x2
    uint32_t* Pb = g_Pp + ((size_t)(split*BB + b)) * SS * 64;
#pragma unroll
    for (int mt = 0; mt < 2; mt++) {
        int i = mw*32 + mt*16 + gid;
#pragma unroll
        for (int n = 0; n < 8; n++) {
            int jp = nw*32 + n*4 + tq;     // pair index = j/2
            Pb[i*64 + jp]     = packbf(pacc[mt][n][0], pacc[mt][n][1]);
            Pb[(i+8)*64 + jp] = packbf(pacc[mt][n][2], pacc[mt][n][3]);
        }
    }
}

// ---- softmax_plus1 + rowsums; sums bf16 split partials; writes A bf16x2 (j-pair-permuted) ----
__global__ void softmax_kernel() {
    __shared__ float wm[4], ws[4];
    int bid = blockIdx.x;
    int b = bid >> 7, i = bid & 127;
    int j = threadIdx.x;
    const float inv_scale = 1.0f / sqrtf((float)(CC * TT));
    int shift = (j & 1) * 16;
    const uint32_t* base = g_Pp + (size_t)b*SS*64 + i*64 + (j >> 1);
    float p = 0.f;
#pragma unroll 16
    for (int sp = 0; sp < NSPLIT; sp++) {
        uint32_t v = base[(size_t)sp*BB*SS*64];
        p += __uint_as_float((v >> shift) << 16);
    }
    float v = (p + g_t2[b*SS + i] + g_t3[b*SS + j] + g_dotb[0]) * inv_scale;
    float m = v;
#pragma unroll
    for (int o = 16; o > 0; o >>= 1) m = fmaxf(m, __shfl_xor_sync(0xffffffff, m, o));
    int w = j >> 5, l = j & 31;
    if (l == 0) wm[w] = m;
    __syncthreads();
    m = fmaxf(fmaxf(wm[0], wm[1]), fmaxf(wm[2], wm[3]));
    float e = expf(v - m);
    float s = e;
#pragma unroll
    for (int o = 16; o > 0; o >>= 1) s += __shfl_xor_sync(0xffffffff, s, o);
    if (l == 0) ws[w] = s;
    __syncthreads();
    s = ws[0] + ws[1] + ws[2] + ws[3];
    float denom = 1.0f + s;
    float val = e / denom;
    float nb = __shfl_xor_sync(0xffffffff, val, 1);
    if (!(j & 1)) {
        int pp = j >> 1;
        g_A[((size_t)b*SS + i)*64 + SLOT(pp)] = packbf(val, nb);
    }
    if (j == 0) g_r[b*SS + i] = s / denom;
}

// ---- stage C: per (b,a,tk128): two t-halves, A resident, Y prefetch overlap ----
#define SC_SMEM ((128*PY + 2*64*PY) * 4)
__global__ void __launch_bounds__(256, 2) stageC_kernel(const float* __restrict__ x,
                                                        const float* __restrict__ alpha,
                                                        const float* __restrict__ b14,
                                                        float* __restrict__ out) {
    extern __shared__ uint32_t smc[];
    uint32_t* As  = smc;               // [128 i][PY]
    uint32_t* Ys0 = smc + 128*PY;      // [64 t'][PY]
    uint32_t* Ys1 = Ys0 + 64*PY;
    uint32_t as_addr = smem_u32(As), ys0_addr = smem_u32(Ys0), ys1_addr = smem_u32(Ys1);
    int tk = blockIdx.x, a = blockIdx.y, b = blockIdx.z;
    int tbase = tk * 128;
    int tid = threadIdx.x, lane = tid & 31, w = tid >> 5;
    int gid = lane >> 2, tq = lane & 3;

    const uint32_t* Ab = g_A + (size_t)b*SS*64;
    const uint32_t* Yb = g_Y2 + (((size_t)(b*CC + a))*TT + tbase) * 64;
    for (int i = tid; i < 128*16; i += 256) {
        int r = i >> 4, c4 = (i & 15) * 4;
        CP_ASYNC16(as_addr + (uint32_t)(r*PY + c4)*4, Ab + r*64 + c4);
    }
    for (int i = tid; i < 64*16; i += 256) {
        int r = i >> 4, c4 = (i & 15) * 4;
        CP_ASYNC16(ys0_addr + (uint32_t)(r*PY + c4)*4, Yb + (size_t)r*64 + c4);
    }
    CP_COMMIT();
    for (int i = tid; i < 64*16; i += 256) {
        int r = i >> 4, c4 = (i & 15) * 4;
        CP_ASYNC16(ys1_addr + (uint32_t)(r*PY + c4)*4, Yb + (size_t)(r + 64)*64 + c4);
    }
    CP_COMMIT();
    CP_WAIT1();
    __syncthreads();

    int i0 = w*16 + gid;
    float ga = g_g[a], ba = b14[a];
    float add0 = g_r[b*SS + i0    ] * ga + ba;
    float add1 = g_r[b*SS + i0 + 8] * ga + ba;

#pragma unroll
    for (int h = 0; h < 2; h++) {
        if (h == 1) { CP_WAIT0(); __syncthreads(); }
        uint32_t* Ys = h ? Ys1 : Ys0;
        int t0 = tbase + h*64;

        float acc[8][4];
#pragma unroll
        for (int n = 0; n < 8; n++)
#pragma unroll
            for (int q = 0; q < 4; q++) acc[n][q] = 0.f;

#pragma unroll
        for (int kg = 0; kg < 8; kg++) {
            uint2 x0 = *(uint2*)&As[(w*16 + gid    )*PY + kg*8 + 2*tq];
            uint2 x1 = *(uint2*)&As[(w*16 + gid + 8)*PY + kg*8 + 2*tq];
#pragma unroll
            for (int n = 0; n < 8; n++) {
                uint2 bv = *(uint2*)&Ys[(n*8 + gid)*PY + kg*8 + 2*tq];
                MMA_BF16(acc[n], x0.x, x1.x, x0.y, x1.y, bv.x, bv.y);
            }
        }

        size_t row0 = (((size_t)b*CC + a)*SS + i0    )*TT + t0;
        size_t row1 = (((size_t)b*CC + a)*SS + i0 + 8)*TT + t0;
        size_t arow0 = ((size_t)a*SS + i0    )*TT + t0;
        size_t arow1 = ((size_t)a*SS + i0 + 8)*TT + t0;
#pragma unroll
        for (int n = 0; n < 8; n++) {
            int tc = n*8 + 2*tq;
            float2 xv0 = *(const float2*)&x[row0 + tc];
            float2 av0 = *(const float2*)&alpha[arow0 + tc];
            float2 o0;
            o0.x = av0.x * (acc[n][0] + add0) + xv0.x;
            o0.y = av0.y * (acc[n][1] + add0) + xv0.y;
            *(float2*)&out[row0 + tc] = o0;
            float2 xv1 = *(const float2*)&x[row1 + tc];
            float2 av1 = *(const float2*)&alpha[arow1 + tc];
            float2 o1;
            o1.x = av1.x * (acc[n][2] + add1) + xv1.x;
            o1.y = av1.y * (acc[n][3] + add1) + xv1.y;
            *(float2*)&out[row1 + tc] = o1;
        }
    }
}

// ---- launcher ----
extern "C" void kernel_launch(void* const* d_in, const int* in_sizes, int n_in,
                              void* d_out, int out_size) {
    const float* x    = (const float*)d_in[0];
    const float* w11  = (const float*)d_in[1];
    const float* b11  = (const float*)d_in[2];
    const float* w12  = (const float*)d_in[3];
    const float* b12  = (const float*)d_in[4];
    const float* w13  = (const float*)d_in[5];
    const float* b13  = (const float*)d_in[6];
    const float* w14  = (const float*)d_in[7];
    const float* b14  = (const float*)d_in[8];
    const float* alpha= (const float*)d_in[9];
    float* out = (float*)d_out;

    cudaFuncSetAttribute((const void*)fusedA_kernel, cudaFuncAttributeMaxDynamicSharedMemorySize, FA_SMEM);
    cudaFuncSetAttribute((const void*)stageC_kernel, cudaFuncAttributeMaxDynamicSharedMemorySize, SC_SMEM);

    prep_kernel<<<256, 256>>>(w11, b11, w12, b12, w13, b13, w14, b14);
    transpose_kernel<<<dim3(TT/32, SS/4, BB), 256>>>(x);
    bias_terms_kernel<<<BB, 128>>>();
    fusedA_kernel<<<dim3(BB, NSPLIT), 256, FA_SMEM>>>();
    softmax_kernel<<<BB*SS, 128>>>();
    stageC_kernel<<<dim3(TT/128, CC, BB), 256, SC_SMEM>>>(x, alpha, b14, out);
}